// round 2
// baseline (speedup 1.0000x reference)
#include <cuda_runtime.h>

#define B_   4
#define N_   4096
#define DIN_ 128
#define H_   64
#define DO_  128
#define BM   64
#define BN   64
#define QS   68   // padded smem row stride (floats), multiple of 4 for float4

// Scratch for projected Q, K, V (device globals: no allocation allowed)
__device__ float g_Q[B_ * N_ * H_];
__device__ float g_K[B_ * N_ * H_];
__device__ float g_V[B_ * N_ * DO_];

// ---------------------------------------------------------------------------
// Stage 1: Q = h@Ws, K = h@Wt, V = h@Wc   (fused; 4 rows per CTA)
// threads 0..63 -> Q cols, 64..127 -> K cols, 128..255 -> V cols (warp-uniform)
// ---------------------------------------------------------------------------
__global__ __launch_bounds__(256) void proj_kernel(
    const float* __restrict__ h, const float* __restrict__ Ws,
    const float* __restrict__ Wt, const float* __restrict__ Wc) {
    __shared__ float sh[4][DIN_];
    const int row0 = blockIdx.x * 4;
    const int tid = threadIdx.x;

    #pragma unroll
    for (int i = tid; i < 4 * DIN_; i += 256)
        sh[i >> 7][i & 127] = h[(size_t)row0 * DIN_ + i];
    __syncthreads();

    const int c = tid;
    const float* W; float* dst; int col, stride;
    if (c < 64)       { W = Ws; dst = g_Q; col = c;       stride = H_;  }
    else if (c < 128) { W = Wt; dst = g_K; col = c - 64;  stride = H_;  }
    else              { W = Wc; dst = g_V; col = c - 128; stride = DO_; }

    float a0 = 0.f, a1 = 0.f, a2 = 0.f, a3 = 0.f;
    const float* wp = W + col;
    #pragma unroll 16
    for (int k = 0; k < DIN_; ++k) {
        float w = wp[k * stride];
        a0 = fmaf(sh[0][k], w, a0);
        a1 = fmaf(sh[1][k], w, a1);
        a2 = fmaf(sh[2][k], w, a2);
        a3 = fmaf(sh[3][k], w, a3);
    }
    dst[(size_t)(row0 + 0) * stride + col] = a0;
    dst[(size_t)(row0 + 1) * stride + col] = a1;
    dst[(size_t)(row0 + 2) * stride + col] = a2;
    dst[(size_t)(row0 + 3) * stride + col] = a3;
}

// ---------------------------------------------------------------------------
// Stage 2: flash attention with adjacency mask.
// Grid (N/BM, B), 256 threads. ty=tid/16 (4 rows each), tx=tid%16.
// S-phase: 4x4 micro-tile of S[64x64]; PV-phase: 4 rows x 8 dims of acc[64x128].
// ---------------------------------------------------------------------------
extern __shared__ float smem[];

__global__ __launch_bounds__(256, 2) void attn_kernel(
    const int* __restrict__ adj, float* __restrict__ out) {
    float* sQ = smem;                 // [64][QS] k-major: sQ[k*QS + r]
    float* sK = sQ + 64 * QS;         // [64][QS] k-major: sK[k*QS + c]
    float* sP = sK + 64 * QS;         // [64][QS] row-major: sP[r*QS + j]
    float* sV = sP + 64 * QS;         // [64][128]

    const int b    = blockIdx.y;
    const int row0 = blockIdx.x * BM;
    const int tid  = threadIdx.x;
    const int ty   = tid >> 4;
    const int tx   = tid & 15;

    const float* Qg = g_Q + (size_t)b * N_ * H_;
    const float* Kg = g_K + (size_t)b * N_ * H_;
    const float* Vg = g_V + (size_t)b * N_ * DO_;

    // Load Q tile transposed into smem (k-major)
    #pragma unroll
    for (int i = tid; i < 64 * 16; i += 256) {
        int r = i >> 4, k4 = (i & 15) << 2;
        float4 q = *reinterpret_cast<const float4*>(Qg + (size_t)(row0 + r) * H_ + k4);
        sQ[(k4 + 0) * QS + r] = q.x;
        sQ[(k4 + 1) * QS + r] = q.y;
        sQ[(k4 + 2) * QS + r] = q.z;
        sQ[(k4 + 3) * QS + r] = q.w;
    }

    float m[4], l[4], acc[4][8];
    #pragma unroll
    for (int i = 0; i < 4; ++i) {
        m[i] = -1e30f; l[i] = 0.f;
        #pragma unroll
        for (int d = 0; d < 8; ++d) acc[i][d] = 0.f;
    }

    for (int jb = 0; jb < N_ / BN; ++jb) {
        const int c0 = jb * BN;
        __syncthreads();   // prior PV done (and Q load on first iter)

        // Load K tile transposed (k-major) + V tile (row-major)
        #pragma unroll
        for (int i = tid; i < 64 * 16; i += 256) {
            int r = i >> 4, k4 = (i & 15) << 2;
            float4 kk = *reinterpret_cast<const float4*>(Kg + (size_t)(c0 + r) * H_ + k4);
            sK[(k4 + 0) * QS + r] = kk.x;
            sK[(k4 + 1) * QS + r] = kk.y;
            sK[(k4 + 2) * QS + r] = kk.z;
            sK[(k4 + 3) * QS + r] = kk.w;
        }
        #pragma unroll
        for (int i = tid; i < 64 * 32; i += 256) {
            int r = i >> 5, d4 = (i & 31) << 2;
            *reinterpret_cast<float4*>(sV + r * DO_ + d4) =
                *reinterpret_cast<const float4*>(Vg + (size_t)(c0 + r) * DO_ + d4);
        }
        __syncthreads();

        // ---- S = Q @ K^T (4x4 per thread) ----
        float s[4][4];
        #pragma unroll
        for (int i = 0; i < 4; ++i)
            #pragma unroll
            for (int j = 0; j < 4; ++j) s[i][j] = 0.f;

        const float* qb = sQ + 4 * ty;
        const float* kb = sK + 4 * tx;
        #pragma unroll 16
        for (int k = 0; k < 64; ++k) {
            float4 a  = *reinterpret_cast<const float4*>(qb + k * QS);
            float4 bv = *reinterpret_cast<const float4*>(kb + k * QS);
            float av[4] = {a.x, a.y, a.z, a.w};
            float bw[4] = {bv.x, bv.y, bv.z, bv.w};
            #pragma unroll
            for (int i = 0; i < 4; ++i)
                #pragma unroll
                for (int j = 0; j < 4; ++j)
                    s[i][j] = fmaf(av[i], bw[j], s[i][j]);
        }

        // ---- mask + online softmax ----
        #pragma unroll
        for (int i = 0; i < 4; ++i) {
            int4 ab = *reinterpret_cast<const int4*>(
                adj + (size_t)(row0 + 4 * ty + i) * N_ + c0 + 4 * tx);
            float t0 = (ab.x > 0) ? s[i][0] : -1e30f;
            float t1 = (ab.y > 0) ? s[i][1] : -1e30f;
            float t2 = (ab.z > 0) ? s[i][2] : -1e30f;
            float t3 = (ab.w > 0) ? s[i][3] : -1e30f;
            float rm = fmaxf(fmaxf(t0, t1), fmaxf(t2, t3));
            #pragma unroll
            for (int off = 8; off > 0; off >>= 1)
                rm = fmaxf(rm, __shfl_xor_sync(0xffffffffu, rm, off));

            float mn = fmaxf(m[i], rm);
            float sc = __expf(m[i] - mn);

            float p0 = (ab.x > 0) ? __expf(s[i][0] - mn) : 0.f;
            float p1 = (ab.y > 0) ? __expf(s[i][1] - mn) : 0.f;
            float p2 = (ab.z > 0) ? __expf(s[i][2] - mn) : 0.f;
            float p3 = (ab.w > 0) ? __expf(s[i][3] - mn) : 0.f;
            *reinterpret_cast<float4*>(sP + (4 * ty + i) * QS + 4 * tx) =
                make_float4(p0, p1, p2, p3);

            float rsum = (p0 + p1) + (p2 + p3);
            #pragma unroll
            for (int off = 8; off > 0; off >>= 1)
                rsum += __shfl_xor_sync(0xffffffffu, rsum, off);

            l[i] = l[i] * sc + rsum;
            m[i] = mn;
            #pragma unroll
            for (int d = 0; d < 8; ++d) acc[i][d] *= sc;
        }
        __syncthreads();

        // ---- PV: acc[4 rows][8 dims] += P @ V ----
        const float* pBase = sP + 4 * ty * QS;
        const float* vBase = sV + 8 * tx;
        #pragma unroll 8
        for (int j = 0; j < 64; ++j) {
            float p0 = pBase[0 * QS + j];
            float p1 = pBase[1 * QS + j];
            float p2 = pBase[2 * QS + j];
            float p3 = pBase[3 * QS + j];
            float4 v0 = *reinterpret_cast<const float4*>(vBase + j * DO_);
            float4 v1 = *reinterpret_cast<const float4*>(vBase + j * DO_ + 4);
            float vv[8] = {v0.x, v0.y, v0.z, v0.w, v1.x, v1.y, v1.z, v1.w};
            float pp[4] = {p0, p1, p2, p3};
            #pragma unroll
            for (int i = 0; i < 4; ++i)
                #pragma unroll
                for (int d = 0; d < 8; ++d)
                    acc[i][d] = fmaf(pp[i], vv[d], acc[i][d]);
        }
    }

    // ---- epilogue: out = acc / l ----
    #pragma unroll
    for (int i = 0; i < 4; ++i) {
        float inv = 1.0f / l[i];
        float* op = out + ((size_t)b * N_ + row0 + 4 * ty + i) * DO_ + 8 * tx;
        float4 o0 = make_float4(acc[i][0] * inv, acc[i][1] * inv,
                                acc[i][2] * inv, acc[i][3] * inv);
        float4 o1 = make_float4(acc[i][4] * inv, acc[i][5] * inv,
                                acc[i][6] * inv, acc[i][7] * inv);
        *reinterpret_cast<float4*>(op)     = o0;
        *reinterpret_cast<float4*>(op + 4) = o1;
    }
}

// ---------------------------------------------------------------------------
extern "C" void kernel_launch(void* const* d_in, const int* in_sizes, int n_in,
                              void* d_out, int out_size) {
    const float* h   = (const float*)d_in[0];
    const int*   adj = (const int*)  d_in[1];
    const float* Ws  = (const float*)d_in[2];
    const float* Wt  = (const float*)d_in[3];
    const float* Wc  = (const float*)d_in[4];
    float* out = (float*)d_out;

    proj_kernel<<<B_ * N_ / 4, 256>>>(h, Ws, Wt, Wc);

    const int smemBytes = (3 * 64 * QS + 64 * DO_) * (int)sizeof(float);  // 84992
    cudaFuncSetAttribute(attn_kernel,
                         cudaFuncAttributeMaxDynamicSharedMemorySize, smemBytes);
    dim3 grid(N_ / BM, B_);
    attn_kernel<<<grid, 256, smemBytes>>>(adj, out);
}